// round 17
// baseline (speedup 1.0000x reference)
#include <cuda_runtime.h>
#include <cuda_bf16.h>
#include <cstdint>

// StimulusLayer: dist[b,o] = max_i |x[b,i] - stim[o,i]| (Chebyshev),
// out = state*0.95 + sigmoid((a-dist)*b).  B=128, I=256, O=4096.
//
// R13 = R12 with the inner compute re-ordered: scalar k outer, 16 independent
// accumulator cells inner -> strictly alternating FADD/FMNMX stream so the
// fma and alu pipes are both busy every cycle (defeat pipe phase-locking).

#define B_DIM 128
#define I_DIM 256
#define O_DIM 4096

#define XPITCH4  65          // x row pitch in float4 (64 + 1 pad)
#define SPITCH4  17          // stim row pitch in float4 (16 + 1 pad)
#define RPITCH   72          // red row pitch in floats (64 + 8 pad)

#define XS_F4    (16 * XPITCH4)            // 1040 f4
#define SS_F4    (64 * SPITCH4)            // per k-group: 1088 f4
#define SMEM_X   0
#define SMEM_S   (XS_F4 * 16)              // bytes
#define SMEM_R   (SMEM_S + 4 * SS_F4 * 16)
#define SMEM_TOT (SMEM_R + 4 * 16 * RPITCH * 4)   // ~104.7 KB

__device__ __forceinline__ void cp_async16(uint32_t saddr, const void* gptr) {
    asm volatile("cp.async.cg.shared.global [%0], [%1], 16;" :: "r"(saddr), "l"(gptr));
}

__global__ __launch_bounds__(256, 2)
void stimulus_kernel(const float* __restrict__ x,
                     const float* __restrict__ stim,
                     const float* __restrict__ a,
                     const float* __restrict__ bvec,
                     const float* __restrict__ state,
                     float* __restrict__ out)
{
    extern __shared__ char smem[];
    float* xs  = (float*)(smem + SMEM_X);            // [16][260] floats
    float* ss  = (float*)(smem + SMEM_S);            // [4][64*68] floats
    float* red = (float*)(smem + SMEM_R);            // [4][16*72] floats

    const int tid  = threadIdx.x;        // 0..255
    const int w    = tid >> 5;           // warp 0..7
    const int lane = tid & 31;
    const int kg   = w >> 1;             // k-group 0..3 (64 k each)
    const int ow   = w & 1;              // o-half 0..1
    const int lb   = lane >> 3;          // 0..3
    const int lo   = lane & 7;           // 0..7

    const int b0 = blockIdx.y * 16;
    const int o0 = blockIdx.x * 64;

    const float4* __restrict__ x4 = (const float4*)x;    // row = 64 f4
    const float4* __restrict__ s4 = (const float4*)stim; // row = 64 f4

    const uint32_t xs_b = (uint32_t)__cvta_generic_to_shared(xs);
    const uint32_t ss_b = (uint32_t)__cvta_generic_to_shared(ss);

    // ---- stage x: 16 rows x 64 f4, 4 per thread ----
    #pragma unroll
    for (int i = 0; i < 4; i++) {
        int idx = tid + 256 * i;                   // 0..1023
        int row = idx >> 6, col = idx & 63;
        cp_async16(xs_b + (row * XPITCH4 + col) * 16,
                   &x4[(b0 + row) * 64 + col]);
    }
    // ---- stage stim: group kg = 64 rows x 16 f4; 2 warps per group ----
    #pragma unroll
    for (int i = 0; i < 16; i++) {
        int idx = lane + 32 * i;                   // 0..511
        int row = ow * 32 + (idx >> 4);            // 0..63
        int col = idx & 15;                        // f4 col in group's 64k
        cp_async16(ss_b + (kg * SS_F4 + row * SPITCH4 + col) * 16,
                   &s4[(o0 + row) * 64 + kg * 16 + col]);
    }
    asm volatile("cp.async.wait_all;" ::: "memory");
    __syncthreads();

    // ---- register mainloop: this warp's 64 k, o-strip ow*32.. ----
    const float* xb = xs + kg * 64;
    const float* sb = ss + kg * (SS_F4 * 4) + (ow * 32) * (SPITCH4 * 4);

    float acc[4][4];
    #pragma unroll
    for (int jb = 0; jb < 4; jb++)
        #pragma unroll
        for (int jo = 0; jo < 4; jo++) acc[jb][jo] = 0.0f;

    #pragma unroll
    for (int k4 = 0; k4 < 16; k4++) {
        float4 xv[4], sv[4];
        #pragma unroll
        for (int jb = 0; jb < 4; jb++)             // 4 x 16B dedup -> 1 wf
            xv[jb] = *(const float4*)&xb[(lb + 4 * jb) * (XPITCH4 * 4) + k4 * 4];
        #pragma unroll
        for (int jo = 0; jo < 4; jo++)             // banks spread -> 1 wf
            sv[jo] = *(const float4*)&sb[(lo + 8 * jo) * (SPITCH4 * 4) + k4 * 4];

        // scalar k outer, 16 independent cells inner:
        // source stream = FADD,FMNMX,FADD,FMNMX,... (1:1 pipe mix everywhere)
        #pragma unroll
        for (int e = 0; e < 4; e++) {
            #pragma unroll
            for (int jb = 0; jb < 4; jb++) {
                const float xe = (e == 0) ? xv[jb].x : (e == 1) ? xv[jb].y :
                                 (e == 2) ? xv[jb].z : xv[jb].w;
                #pragma unroll
                for (int jo = 0; jo < 4; jo++) {
                    const float se = (e == 0) ? sv[jo].x : (e == 1) ? sv[jo].y :
                                     (e == 2) ? sv[jo].z : sv[jo].w;
                    acc[jb][jo] = fmaxf(acc[jb][jo], fabsf(xe - se));
                }
            }
        }
    }

    // ---- write k-group partials (pitch 72: conflict-free) ----
    #pragma unroll
    for (int jb = 0; jb < 4; jb++) {
        const int b = lb + 4 * jb;
        #pragma unroll
        for (int jo = 0; jo < 4; jo++) {
            const int o = ow * 32 + lo + 8 * jo;
            red[kg * (16 * RPITCH) + b * RPITCH + o] = acc[jb][jo];
        }
    }
    __syncthreads();

    // ---- reduce 4 k-groups + sigmoid + state (4 outputs/thread) ----
    #pragma unroll
    for (int i = 0; i < 4; i++) {
        const int idx = tid + 256 * i;             // 0..1023
        const int b   = idx >> 6;                  // 0..15
        const int o   = idx & 63;
        float d = red[0 * (16 * RPITCH) + b * RPITCH + o];
        d = fmaxf(d, red[1 * (16 * RPITCH) + b * RPITCH + o]);
        d = fmaxf(d, red[2 * (16 * RPITCH) + b * RPITCH + o]);
        d = fmaxf(d, red[3 * (16 * RPITCH) + b * RPITCH + o]);
        const int og = o0 + o;
        const float z   = (a[og] - d) * bvec[og];
        const float val = 1.0f / (1.0f + __expf(-z));
        const long  g   = (long)(b0 + b) * O_DIM + og;
        out[g] = state[g] * 0.95f + val;           // coalesced 128B
    }
}

extern "C" void kernel_launch(void* const* d_in, const int* in_sizes, int n_in,
                              void* d_out, int out_size)
{
    const float* x     = (const float*)d_in[0];   // (128, 256)
    const float* stim  = (const float*)d_in[1];   // (4096, 256)
    const float* a     = (const float*)d_in[2];   // (4096,)
    const float* bvec  = (const float*)d_in[3];   // (4096,)
    const float* state = (const float*)d_in[4];   // (128, 4096)
    float* out = (float*)d_out;                   // (128, 4096)

    static int smem_set = 0;                      // idempotent attribute set
    if (!smem_set) {
        cudaFuncSetAttribute(stimulus_kernel,
                             cudaFuncAttributeMaxDynamicSharedMemorySize, SMEM_TOT);
        smem_set = 1;
    }

    dim3 grid(O_DIM / 64, B_DIM / 16);            // 64 x 8 = 512 blocks
    stimulus_kernel<<<grid, 256, SMEM_TOT>>>(x, stim, a, bvec, state, out);
}